// round 16
// baseline (speedup 1.0000x reference)
#include <cuda_runtime.h>
#include <cuda_bf16.h>

#define THICKNESS 0.00047f

// Merged gather: row [3i, 3i+3) fits one aligned float4 iff (3i)&3 <= 1.
// Else parity float2+float (second load hits same L1 line -> merged miss).
__device__ __forceinline__ float3 load_vert(const float* __restrict__ pos, int i) {
    unsigned base = 3u * (unsigned)i;
    unsigned off = base & 3u;
    float x, y, z;
    if (off <= 1u) {
        float4 q = __ldg((const float4*)(pos + (base & ~3u)));
        x = off ? q.y : q.x;
        y = off ? q.z : q.y;
        z = off ? q.w : q.z;
    } else {
        bool o2 = (off == 2u);
        float2 ab = __ldg((const float2*)(pos + base + (o2 ? 0u : 1u)));
        float  c  = __ldg(pos + base + (o2 ? 2u : 0u));
        x = o2 ? ab.x : c;
        y = o2 ? ab.y : ab.x;
        z = o2 ? c    : ab.y;
    }
    return make_float3(x, y, z);
}

// Same merged trick for the int32 faces row.
__device__ __forceinline__ void load_face_row(const int* __restrict__ faces, int f,
                                              int& i0, int& i1, int& i2) {
    unsigned base = 3u * (unsigned)f;
    unsigned off = base & 3u;
    if (off <= 1u) {
        int4 q = __ldcs((const int4*)(faces + (base & ~3u)));
        i0 = off ? q.y : q.x;
        i1 = off ? q.z : q.y;
        i2 = off ? q.w : q.z;
    } else {
        bool o2 = (off == 2u);
        int2 ab = __ldcs((const int2*)(faces + base + (o2 ? 0u : 1u)));
        int  c  = __ldcs(faces + base + (o2 ? 2u : 0u));
        i0 = o2 ? ab.x : c;
        i1 = o2 ? ab.y : ab.x;
        i2 = o2 ? c    : ab.y;
    }
}

__global__ __launch_bounds__(512)
void stvk_face_kernel(
    const float* __restrict__ pos,        // [V,3]
    const int* __restrict__ faces,        // [F,3] int32
    const float* __restrict__ dminv,      // [F,2,2]
    const float* __restrict__ area,       // [F,1]
    const float* __restrict__ mu_p,
    const float* __restrict__ lam_p,
    float* __restrict__ per_vert,         // [V]
    float* __restrict__ loss,
    int F)
{
    int f = blockIdx.x * blockDim.x + threadIdx.x;
    float e = 0.0f;
    if (f < F) {
        int i0, i1, i2;
        load_face_row(faces, f, i0, i1, i2);

        // gathers first: maximal MLP on the random-latency path
        float3 p0 = load_vert(pos, i0);
        float3 p1 = load_vert(pos, i1);
        float3 p2 = load_vert(pos, i2);

        float4 dm = __ldcs((const float4*)(dminv) + f);
        float arv = __ldcs(&area[f]);

        float d1x = p0.x - p2.x, d1y = p0.y - p2.y, d1z = p0.z - p2.z;
        float d2x = p1.x - p2.x, d2y = p1.y - p2.y, d2z = p1.z - p2.z;

        float a = dm.x, b = dm.y, c = dm.z, d = dm.w;
        float F0x = d1x * a + d2x * c;
        float F0y = d1y * a + d2y * c;
        float F0z = d1z * a + d2z * c;
        float F1x = d1x * b + d2x * d;
        float F1y = d1y * b + d2y * d;
        float F1z = d1z * b + d2z * d;

        float g00 = 0.5f * (F0x * F0x + F0y * F0y + F0z * F0z - 1.0f);
        float g01 = 0.5f * (F0x * F1x + F0y * F1y + F0z * F1z);
        float g11 = 0.5f * (F1x * F1x + F1y * F1y + F1z * F1z - 1.0f);
        float tr = g00 + g11;

        float mu = __ldg(mu_p);
        float lam = __ldg(lam_p);

        float s00 = mu * g00 + 0.5f * lam * tr;
        float s01 = mu * g01;
        float s11 = mu * g11 + 0.5f * lam * tr;

        float ed = s00 * g00 + 2.0f * s01 * g01 + s11 * g11;
        e = arv * THICKNESS * ed;

        float e3 = e * (1.0f / 3.0f);
        atomicAdd(&per_vert[i0], e3);
        atomicAdd(&per_vert[i1], e3);
        atomicAdd(&per_vert[i2], e3);
    }

    // block-reduce -> one loss atomic per block
    float v = e;
    #pragma unroll
    for (int off = 16; off > 0; off >>= 1)
        v += __shfl_down_sync(0xFFFFFFFFu, v, off);

    __shared__ float smem[16];
    int lane = threadIdx.x & 31;
    int wid = threadIdx.x >> 5;
    if (lane == 0) smem[wid] = v;
    __syncthreads();
    if (wid == 0) {
        float w = (lane < (blockDim.x >> 5)) ? smem[lane] : 0.0f;
        #pragma unroll
        for (int off = 8; off > 0; off >>= 1)
            w += __shfl_down_sync(0xFFFFFFFFu, w, off);
        if (lane == 0 && loss != nullptr)
            atomicAdd(loss, w);
    }
}

extern "C" void kernel_launch(void* const* d_in, const int* in_sizes, int n_in,
                              void* d_out, int out_size) {
    const float* pos = (const float*)d_in[0];
    const int* faces = (const int*)d_in[1];
    const float* dminv = (const float*)d_in[2];
    const float* area = (const float*)d_in[3];
    const float* mu_p = (const float*)d_in[4];
    const float* lam_p = (const float*)d_in[5];

    int V = in_sizes[0] / 3;
    int F = in_sizes[1] / 3;

    float* out = (float*)d_out;
    float* per_vert = out + (out_size - V);
    float* loss = (out_size > V) ? out : nullptr;

    cudaMemsetAsync(d_out, 0, (size_t)out_size * sizeof(float));

    int blocks = (F + 511) / 512;
    stvk_face_kernel<<<blocks, 512>>>(pos, faces, dminv, area, mu_p, lam_p,
                                      per_vert, loss, F);
}

// round 17
// speedup vs baseline: 1.0367x; 1.0367x over previous
#include <cuda_runtime.h>
#include <cuda_bf16.h>

#define THICKNESS 0.00047f

// Merged gather: row [3i, 3i+3) fits one aligned float4 iff (3i)&3 <= 1.
// Else parity float2+float (second load hits same L1 line -> merged miss).
__device__ __forceinline__ float3 load_vert(const float* __restrict__ pos, int i) {
    unsigned base = 3u * (unsigned)i;
    unsigned off = base & 3u;
    float x, y, z;
    if (off <= 1u) {
        float4 q = __ldg((const float4*)(pos + (base & ~3u)));
        x = off ? q.y : q.x;
        y = off ? q.z : q.y;
        z = off ? q.w : q.z;
    } else {
        bool o2 = (off == 2u);
        float2 ab = __ldg((const float2*)(pos + base + (o2 ? 0u : 1u)));
        float  c  = __ldg(pos + base + (o2 ? 2u : 0u));
        x = o2 ? ab.x : c;
        y = o2 ? ab.y : ab.x;
        z = o2 ? c    : ab.y;
    }
    return make_float3(x, y, z);
}

// Same merged trick for the int32 faces row.
__device__ __forceinline__ void load_face_row(const int* __restrict__ faces, int f,
                                              int& i0, int& i1, int& i2) {
    unsigned base = 3u * (unsigned)f;
    unsigned off = base & 3u;
    if (off <= 1u) {
        int4 q = __ldcs((const int4*)(faces + (base & ~3u)));
        i0 = off ? q.y : q.x;
        i1 = off ? q.z : q.y;
        i2 = off ? q.w : q.z;
    } else {
        bool o2 = (off == 2u);
        int2 ab = __ldcs((const int2*)(faces + base + (o2 ? 0u : 1u)));
        int  c  = __ldcs(faces + base + (o2 ? 2u : 0u));
        i0 = o2 ? ab.x : c;
        i1 = o2 ? ab.y : ab.x;
        i2 = o2 ? c    : ab.y;
    }
}

__global__ __launch_bounds__(512)
void stvk_face_kernel(
    const float* __restrict__ pos,        // [V,3]
    const int* __restrict__ faces,        // [F,3] int32
    const float* __restrict__ dminv,      // [F,2,2]
    const float* __restrict__ area,       // [F,1]
    const float* __restrict__ mu_p,
    const float* __restrict__ lam_p,
    float* __restrict__ per_vert,         // [V]
    float* __restrict__ loss,
    int F)
{
    int f = blockIdx.x * blockDim.x + threadIdx.x;
    float e = 0.0f;
    if (f < F) {
        int i0, i1, i2;
        load_face_row(faces, f, i0, i1, i2);

        // gathers first: maximal MLP on the random-latency path
        float3 p0 = load_vert(pos, i0);
        float3 p1 = load_vert(pos, i1);
        float3 p2 = load_vert(pos, i2);

        float4 dm = __ldcs((const float4*)(dminv) + f);
        float arv = __ldcs(&area[f]);

        float d1x = p0.x - p2.x, d1y = p0.y - p2.y, d1z = p0.z - p2.z;
        float d2x = p1.x - p2.x, d2y = p1.y - p2.y, d2z = p1.z - p2.z;

        float a = dm.x, b = dm.y, c = dm.z, d = dm.w;
        float F0x = d1x * a + d2x * c;
        float F0y = d1y * a + d2y * c;
        float F0z = d1z * a + d2z * c;
        float F1x = d1x * b + d2x * d;
        float F1y = d1y * b + d2y * d;
        float F1z = d1z * b + d2z * d;

        float g00 = 0.5f * (F0x * F0x + F0y * F0y + F0z * F0z - 1.0f);
        float g01 = 0.5f * (F0x * F1x + F0y * F1y + F0z * F1z);
        float g11 = 0.5f * (F1x * F1x + F1y * F1y + F1z * F1z - 1.0f);
        float tr = g00 + g11;

        float mu = __ldg(mu_p);
        float lam = __ldg(lam_p);

        float s00 = mu * g00 + 0.5f * lam * tr;
        float s01 = mu * g01;
        float s11 = mu * g11 + 0.5f * lam * tr;

        float ed = s00 * g00 + 2.0f * s01 * g01 + s11 * g11;
        e = arv * THICKNESS * ed;

        float e3 = e * (1.0f / 3.0f);
        atomicAdd(&per_vert[i0], e3);
        atomicAdd(&per_vert[i1], e3);
        atomicAdd(&per_vert[i2], e3);
    }

    // block-reduce -> one loss atomic per block
    float v = e;
    #pragma unroll
    for (int off = 16; off > 0; off >>= 1)
        v += __shfl_down_sync(0xFFFFFFFFu, v, off);

    __shared__ float smem[16];
    int lane = threadIdx.x & 31;
    int wid = threadIdx.x >> 5;
    if (lane == 0) smem[wid] = v;
    __syncthreads();
    if (wid == 0) {
        float w = (lane < (blockDim.x >> 5)) ? smem[lane] : 0.0f;
        #pragma unroll
        for (int off = 8; off > 0; off >>= 1)
            w += __shfl_down_sync(0xFFFFFFFFu, w, off);
        if (lane == 0 && loss != nullptr)
            atomicAdd(loss, w);
    }
}

extern "C" void kernel_launch(void* const* d_in, const int* in_sizes, int n_in,
                              void* d_out, int out_size) {
    const float* pos = (const float*)d_in[0];
    const int* faces = (const int*)d_in[1];
    const float* dminv = (const float*)d_in[2];
    const float* area = (const float*)d_in[3];
    const float* mu_p = (const float*)d_in[4];
    const float* lam_p = (const float*)d_in[5];

    int V = in_sizes[0] / 3;
    int F = in_sizes[1] / 3;

    float* out = (float*)d_out;
    float* per_vert = out + (out_size - V);
    float* loss = (out_size > V) ? out : nullptr;

    cudaMemsetAsync(d_out, 0, (size_t)out_size * sizeof(float));

    int blocks = (F + 511) / 512;
    stvk_face_kernel<<<blocks, 512>>>(pos, faces, dminv, area, mu_p, lam_p,
                                      per_vert, loss, F);
}